// round 1
// baseline (speedup 1.0000x reference)
#include <cuda_runtime.h>
#include <cstdint>
#include <cstddef>

#define NCH 128
#define MID 128
#define MAXN 50000

// ---------------- scratch (static device arrays; no allocation) ----------------
__device__ float g_h[(size_t)MAXN * NCH];
__device__ float g_agg[(size_t)MAXN * NCH];
__device__ float g_t[(size_t)MAXN * NCH];
__device__ int   g_is64;

// ---------------- helpers ----------------
__device__ __forceinline__ unsigned f2tf(float f) {
    unsigned u;
    asm("cvt.rna.tf32.f32 %0, %1;" : "=r"(u) : "f"(f));
    return u;
}

__device__ __forceinline__ void mma8(float c[4],
                                     unsigned a0, unsigned a1, unsigned a2, unsigned a3,
                                     unsigned b0, unsigned b1) {
    asm volatile(
        "mma.sync.aligned.m16n8k8.row.col.f32.tf32.tf32.f32 "
        "{%0,%1,%2,%3},{%4,%5,%6,%7},{%8,%9},{%0,%1,%2,%3};\n"
        : "+f"(c[0]), "+f"(c[1]), "+f"(c[2]), "+f"(c[3])
        : "r"(a0), "r"(a1), "r"(a2), "r"(a3), "r"(b0), "r"(b1));
}

__device__ __forceinline__ float gelu_exact(float x) {
    return 0.5f * x * (1.0f + erff(x * 0.70710678118654752f));
}

// sin/cos with explicit Cody-Waite reduction mod 2*pi (fast-math safe; |x| < ~2e4)
__device__ __forceinline__ float sin_acc(float x) {
    const float INV2PI = 0.15915494309189535f;
    const float A = 6.2831854820251465f;     // fp32(2*pi)
    const float B = -1.7484555e-7f;          // 2*pi - A
    float n = rintf(x * INV2PI);
    float r = fmaf(-n, A, x);
    r = fmaf(-n, B, r);
    return sinf(r);
}
__device__ __forceinline__ float cos_acc(float x) {
    const float INV2PI = 0.15915494309189535f;
    const float A = 6.2831854820251465f;
    const float B = -1.7484555e-7f;
    float n = rintf(x * INV2PI);
    float r = fmaf(-n, A, x);
    r = fmaf(-n, B, r);
    return cosf(r);
}

// ---------------- misc kernels ----------------
__global__ void zero_kernel(float4* p, int n4) {
    int i = blockIdx.x * blockDim.x + threadIdx.x;
    if (i < n4) p[i] = make_float4(0.f, 0.f, 0.f, 0.f);
}

__global__ void detect_kernel(const void* ei) {
    // int32 data reinterpreted as int64 combines two small ints -> >= 2^32 almost surely
    const long long* p = (const long long*)ei;
    bool is64 = true;
    for (int i = 0; i < 8; i++) {
        long long v = p[i];
        if (v < 0 || v >= (1LL << 31)) is64 = false;
    }
    g_is64 = is64 ? 1 : 0;
}

// ---------------- fp32 node GEMM:  C = act(A (+A2) @ W + bias) ----------------
__global__ void __launch_bounds__(256)
node_gemm(const float* __restrict__ A, const float* __restrict__ A2,
          const float* __restrict__ W, const float* __restrict__ bias,
          float* __restrict__ C, int M, int act) {
    __shared__ float sAT[32][132];  // [k][m] transposed A chunk
    __shared__ float sW[32][132];   // [k][n]
    const int tid = threadIdx.x;
    const int m0 = blockIdx.x * 128;
    const int tm = tid & 15, tn = tid >> 4;

    float acc[8][8];
#pragma unroll
    for (int i = 0; i < 8; i++)
#pragma unroll
        for (int j = 0; j < 8; j++) acc[i][j] = 0.f;

    for (int kc = 0; kc < 4; kc++) {
#pragma unroll
        for (int i = 0; i < 4; i++) {
            int lin = tid + i * 256;
            int row = lin >> 3, c4 = lin & 7;
            float4 v = make_float4(0.f, 0.f, 0.f, 0.f);
            if (m0 + row < M) {
                v = *(const float4*)(A + (size_t)(m0 + row) * NCH + kc * 32 + c4 * 4);
                if (A2) {
                    float4 w = *(const float4*)(A2 + (size_t)(m0 + row) * NCH + kc * 32 + c4 * 4);
                    v.x += w.x; v.y += w.y; v.z += w.z; v.w += w.w;
                }
            }
            sAT[c4 * 4 + 0][row] = v.x;
            sAT[c4 * 4 + 1][row] = v.y;
            sAT[c4 * 4 + 2][row] = v.z;
            sAT[c4 * 4 + 3][row] = v.w;
        }
#pragma unroll
        for (int i = 0; i < 4; i++) {
            int lin = tid + i * 256;
            int kr = lin >> 5, n4 = lin & 31;
            float4 v = *(const float4*)(W + (size_t)(kc * 32 + kr) * NCH + n4 * 4);
            *(float4*)&sW[kr][n4 * 4] = v;
        }
        __syncthreads();
#pragma unroll 8
        for (int k = 0; k < 32; k++) {
            float a[8], b[8];
            *(float4*)&a[0] = *(float4*)&sAT[k][tm * 8];
            *(float4*)&a[4] = *(float4*)&sAT[k][tm * 8 + 4];
            *(float4*)&b[0] = *(float4*)&sW[k][tn * 8];
            *(float4*)&b[4] = *(float4*)&sW[k][tn * 8 + 4];
#pragma unroll
            for (int i = 0; i < 8; i++)
#pragma unroll
                for (int j = 0; j < 8; j++) acc[i][j] = fmaf(a[i], b[j], acc[i][j]);
        }
        __syncthreads();
    }

#pragma unroll
    for (int i = 0; i < 8; i++) {
        int row = m0 + tm * 8 + i;
        if (row < M) {
#pragma unroll
            for (int j = 0; j < 8; j++) {
                float v = acc[i][j] + __ldg(&bias[tn * 8 + j]);
                if (act) v = fmaxf(v, 0.f);
                C[(size_t)row * NCH + tn * 8 + j] = v;
            }
        }
    }
}

// ---------------- fused edge kernel ----------------
// Per block: 128 edges. Three chained tf32 MMA GEMMs (288->128 gelu, 128->128 gelu,
// 128->128) with intermediates in SMEM, then vectorized red.global scatter into agg.
#define SB_STRIDE 136
#define SM_STRIDE 132
#define SA_STRIDE 36
// floats: sB 32*136=4352, sM 128*132=16896, sA 128*36=4608, sR 128, sBias 128, sSrc 128, sDst 128
#define SMEM_EDGE_BYTES ((4352 + 16896 + 4608 + 128 + 128 + 128 + 128) * 4)

__device__ __forceinline__ void init_acc(float acc[4][4][4], const float* sBias, int wn, int lane) {
#pragma unroll
    for (int nt = 0; nt < 4; nt++) {
        int c = wn * 32 + nt * 8 + (lane & 3) * 2;
        float x0 = sBias[c], x1 = sBias[c + 1];
#pragma unroll
        for (int mt = 0; mt < 4; mt++) {
            acc[mt][nt][0] = x0; acc[mt][nt][1] = x1;
            acc[mt][nt][2] = x0; acc[mt][nt][3] = x1;
        }
    }
}

__device__ __forceinline__ void epi_store(float acc[4][4][4], float* sM,
                                          int wm, int wn, int lane, int applyGelu) {
#pragma unroll
    for (int mt = 0; mt < 4; mt++) {
        int r0 = wm * 64 + mt * 16 + (lane >> 2);
#pragma unroll
        for (int nt = 0; nt < 4; nt++) {
            int c = wn * 32 + nt * 8 + (lane & 3) * 2;
            float v0 = acc[mt][nt][0], v1 = acc[mt][nt][1];
            float v2 = acc[mt][nt][2], v3 = acc[mt][nt][3];
            if (applyGelu) {
                v0 = gelu_exact(v0); v1 = gelu_exact(v1);
                v2 = gelu_exact(v2); v3 = gelu_exact(v3);
            }
            *(float2*)&sM[r0 * SM_STRIDE + c] = make_float2(v0, v1);
            *(float2*)&sM[(r0 + 8) * SM_STRIDE + c] = make_float2(v2, v3);
        }
    }
}

// K=128 GEMM with A in sM, weights streamed into sB
__device__ __forceinline__ void gemm_sm(float acc[4][4][4], const float* sM, float* sB,
                                        const float* __restrict__ Wp,
                                        int wm, int wn, int lane, int tid) {
#pragma unroll 1
    for (int kc = 0; kc < 4; kc++) {
#pragma unroll
        for (int i = 0; i < 4; i++) {
            int lin = tid + i * 256;
            int kr = lin >> 5, n4 = lin & 31;
            float4 v = *(const float4*)(Wp + (size_t)(kc * 32 + kr) * NCH + n4 * 4);
            *(float4*)&sB[kr * SB_STRIDE + n4 * 4] = v;
        }
        __syncthreads();
#pragma unroll
        for (int kk = 0; kk < 4; kk++) {
            int kB = kk * 8;
            int kA = kc * 32 + kB;
            unsigned bf[4][2];
#pragma unroll
            for (int nt = 0; nt < 4; nt++) {
                int n = wn * 32 + nt * 8 + (lane >> 2);
                bf[nt][0] = f2tf(sB[(kB + (lane & 3)) * SB_STRIDE + n]);
                bf[nt][1] = f2tf(sB[(kB + 4 + (lane & 3)) * SB_STRIDE + n]);
            }
#pragma unroll
            for (int mt = 0; mt < 4; mt++) {
                const float* ap = sM + (wm * 64 + mt * 16 + (lane >> 2)) * SM_STRIDE + kA + (lane & 3);
                unsigned a0 = f2tf(ap[0]);
                unsigned a1 = f2tf(ap[8 * SM_STRIDE]);
                unsigned a2 = f2tf(ap[4]);
                unsigned a3 = f2tf(ap[8 * SM_STRIDE + 4]);
#pragma unroll
                for (int nt = 0; nt < 4; nt++)
                    mma8(acc[mt][nt], a0, a1, a2, a3, bf[nt][0], bf[nt][1]);
            }
        }
        __syncthreads();
    }
}

__global__ void __launch_bounds__(256)
edge_kernel(const void* __restrict__ ei_raw, const float* __restrict__ eattr,
            const float* __restrict__ xpos, const float* __restrict__ h,
            float* __restrict__ agg,
            const float* __restrict__ mw1, const float* __restrict__ mb1,
            const float* __restrict__ mw2, const float* __restrict__ mb2,
            const float* __restrict__ mw3, const float* __restrict__ mb3,
            int E) {
    extern __shared__ float smem[];
    float* sB = smem;                          // 32 x 136
    float* sM = sB + 32 * SB_STRIDE;           // 128 x 132
    float* sA = sM + 128 * SM_STRIDE;          // 128 x 36
    float* sR = sA + 128 * SA_STRIDE;          // 128
    float* sBias = sR + 128;                   // 128
    int* sSrc = (int*)(sBias + 128);           // 128
    int* sDst = sSrc + 128;                    // 128

    const int tid = threadIdx.x;
    const int lane = tid & 31;
    const int warp = tid >> 5;
    const int wm = warp >> 2;  // 0..1  (M 64-row slab)
    const int wn = warp & 3;   // 0..3  (N 32-col slab)
    const int e0 = blockIdx.x * 128;
    const int is64 = g_is64;

    // prologue: indices, radial distance, bias for stage 1
    if (tid < 128) {
        int e = e0 + tid;
        int s = 0, d = -1;
        float r = 0.f;
        if (e < E) {
            if (is64) {
                const long long* p = (const long long*)ei_raw;
                s = (int)p[e];
                d = (int)p[(size_t)E + e];
            } else {
                const int* p = (const int*)ei_raw;
                s = p[e];
                d = p[(size_t)E + e];
            }
            float dx = xpos[3 * d + 0] - xpos[3 * s + 0];
            float dy = xpos[3 * d + 1] - xpos[3 * s + 1];
            float dz = xpos[3 * d + 2] - xpos[3 * s + 2];
            r = sqrtf(dx * dx + dy * dy + dz * dz);
        }
        sSrc[tid] = s;
        sDst[tid] = d;
        sR[tid] = r;
        sBias[tid] = mb1[tid];
    }
    __syncthreads();

    float acc[4][4][4];
    init_acc(acc, sBias, wn, lane);

    // ---------------- stage 1: msg_in[128 x 288] @ mw1 + mb1, gelu ----------------
#pragma unroll 1
    for (int kc = 0; kc < 9; kc++) {
        if (kc == 0) {
            // sin/cos features (cols 0..31)
#pragma unroll
            for (int i = 0; i < 16; i++) {
                int lin = tid + i * 256;
                int row = lin >> 5, col = lin & 31;
                int j = col & 15;
                float omega = 10.f * exp2f(7.f - 0.875f * (float)j);
                float feat = sR[row] * omega;
                sA[row * SA_STRIDE + col] = (col < 16) ? sin_acc(feat) : cos_acc(feat);
            }
        } else if (kc <= 4) {
            // edge_attr cols (32..159)
#pragma unroll
            for (int i = 0; i < 4; i++) {
                int lin = tid + i * 256;
                int row = lin >> 3, c4 = lin & 7;
                float4 v = make_float4(0.f, 0.f, 0.f, 0.f);
                int e = e0 + row;
                if (e < E)
                    v = *(const float4*)(eattr + (size_t)e * NCH + (kc - 1) * 32 + c4 * 4);
                *(float4*)&sA[row * SA_STRIDE + c4 * 4] = v;
            }
        } else {
            // h[src] gather (cols 160..287)
#pragma unroll
            for (int i = 0; i < 4; i++) {
                int lin = tid + i * 256;
                int row = lin >> 3, c4 = lin & 7;
                int s = sSrc[row];
                float4 v = *(const float4*)(h + (size_t)s * NCH + (kc - 5) * 32 + c4 * 4);
                *(float4*)&sA[row * SA_STRIDE + c4 * 4] = v;
            }
        }
        // stream weight chunk
        const float* Wp = mw1 + (size_t)kc * 32 * NCH;
#pragma unroll
        for (int i = 0; i < 4; i++) {
            int lin = tid + i * 256;
            int kr = lin >> 5, n4 = lin & 31;
            float4 v = *(const float4*)(Wp + (size_t)kr * NCH + n4 * 4);
            *(float4*)&sB[kr * SB_STRIDE + n4 * 4] = v;
        }
        __syncthreads();
#pragma unroll
        for (int kk = 0; kk < 4; kk++) {
            int k = kk * 8;
            unsigned bf[4][2];
#pragma unroll
            for (int nt = 0; nt < 4; nt++) {
                int n = wn * 32 + nt * 8 + (lane >> 2);
                bf[nt][0] = f2tf(sB[(k + (lane & 3)) * SB_STRIDE + n]);
                bf[nt][1] = f2tf(sB[(k + 4 + (lane & 3)) * SB_STRIDE + n]);
            }
#pragma unroll
            for (int mt = 0; mt < 4; mt++) {
                const float* ap = sA + (wm * 64 + mt * 16 + (lane >> 2)) * SA_STRIDE + k + (lane & 3);
                unsigned a0 = f2tf(ap[0]);
                unsigned a1 = f2tf(ap[8 * SA_STRIDE]);
                unsigned a2 = f2tf(ap[4]);
                unsigned a3 = f2tf(ap[8 * SA_STRIDE + 4]);
#pragma unroll
                for (int nt = 0; nt < 4; nt++)
                    mma8(acc[mt][nt], a0, a1, a2, a3, bf[nt][0], bf[nt][1]);
            }
        }
        __syncthreads();
    }
    epi_store(acc, sM, wm, wn, lane, 1);
    __syncthreads();

    // ---------------- stage 2 ----------------
    if (tid < 128) sBias[tid] = mb2[tid];
    __syncthreads();
    init_acc(acc, sBias, wn, lane);
    gemm_sm(acc, sM, sB, mw2, wm, wn, lane, tid);
    epi_store(acc, sM, wm, wn, lane, 1);
    __syncthreads();

    // ---------------- stage 3 ----------------
    if (tid < 128) sBias[tid] = mb3[tid];
    __syncthreads();
    init_acc(acc, sBias, wn, lane);
    gemm_sm(acc, sM, sB, mw3, wm, wn, lane, tid);
    epi_store(acc, sM, wm, wn, lane, 0);
    __syncthreads();

    // ---------------- scatter: agg[dst] += m  (vectorized reduction) ----------------
#pragma unroll
    for (int i = 0; i < 16; i++) {
        int lin = tid + i * 256;
        int row = lin >> 5, c4 = lin & 31;
        int d = sDst[row];
        if (d >= 0) {
            float4 v = *(float4*)&sM[row * SM_STRIDE + c4 * 4];
            float* p = agg + (size_t)d * NCH + c4 * 4;
            asm volatile("red.global.add.v4.f32 [%0], {%1,%2,%3,%4};" ::
                             "l"(p), "f"(v.x), "f"(v.y), "f"(v.z), "f"(v.w)
                         : "memory");
        }
    }
}

// ---------------- launch ----------------
extern "C" void kernel_launch(void* const* d_in, const int* in_sizes, int n_in,
                              void* d_out, int out_size) {
    const float* x     = (const float*)d_in[0];
    const void*  ei    = d_in[1];
    const float* eattr = (const float*)d_in[2];
    const float* xpos  = (const float*)d_in[3];
    const float* w1  = (const float*)d_in[4];
    const float* b1  = (const float*)d_in[5];
    const float* mw1 = (const float*)d_in[6];
    const float* mb1 = (const float*)d_in[7];
    const float* mw2 = (const float*)d_in[8];
    const float* mb2 = (const float*)d_in[9];
    const float* mw3 = (const float*)d_in[10];
    const float* mb3 = (const float*)d_in[11];
    const float* w2  = (const float*)d_in[12];
    const float* b2  = (const float*)d_in[13];
    const float* w3  = (const float*)d_in[14];
    const float* b3  = (const float*)d_in[15];

    int N = in_sizes[0] / NCH;
    int E = in_sizes[1] / 2;
    float* out = (float*)d_out;

    float *hptr, *aptr, *tptr;
    cudaGetSymbolAddress((void**)&hptr, g_h);
    cudaGetSymbolAddress((void**)&aptr, g_agg);
    cudaGetSymbolAddress((void**)&tptr, g_t);

    cudaFuncSetAttribute(edge_kernel, cudaFuncAttributeMaxDynamicSharedMemorySize,
                         SMEM_EDGE_BYTES);

    detect_kernel<<<1, 1>>>(ei);

    int n4 = N * NCH / 4;
    zero_kernel<<<(n4 + 255) / 256, 256>>>((float4*)aptr, n4);

    node_gemm<<<(N + 127) / 128, 256>>>(x, nullptr, w1, b1, hptr, N, 0);

    edge_kernel<<<(E + 127) / 128, 256, SMEM_EDGE_BYTES>>>(
        ei, eattr, xpos, hptr, aptr, mw1, mb1, mw2, mb2, mw3, mb3, E);

    node_gemm<<<(N + 127) / 128, 256>>>(hptr, aptr, w2, b2, tptr, N, 1);
    node_gemm<<<(N + 127) / 128, 256>>>(tptr, nullptr, w3, b3, out, N, 0);
}